// round 10
// baseline (speedup 1.0000x reference)
#include <cuda_runtime.h>
#include <cstdint>

// Problem constants
#define KTOT  8192
#define WNUM  32
#define TDIM  512
#define FNUM  12
#define VDIM  512
#define BATCH 8

// Phase-1 tiling
#define KC      32                 // k per chunk
#define NCHUNK  (KTOT / KC)        // 256
#define DTILE   64
#define NDTILE  (TDIM / DTILE)     // 8
#define NWORK   37                 // workers per d-tile (296 = 8*37 CTAs)
#define STAGE_K 4
#define SPC     (KC / STAGE_K)     // 8 stages per chunk
#define TILE_F  (WNUM * DTILE)     // 2048 floats = 8KB per k
#define NBUF    3
#define SMEM_BYTES (NBUF * STAGE_K * TILE_F * 4)   // 96 KB

// Partial argmin results per (worker-residue, b, d)
__device__ float g_pval[NWORK][BATCH][TDIM];
__device__ int   g_pidx[NWORK][BATCH][TDIM];
__device__ int   g_idx[BATCH * TDIM];

// Raw full-range MUFU log2 (validated: rel_err 0.0 across rounds).
__device__ __forceinline__ float flg2_fast(float x) {
    float l;
    asm("lg2.approx.f32 %0, %1;" : "=f"(l) : "f"(x));
    return l;
}

// Exact-exponent log2 (prologue only, cached query logs).
__device__ __forceinline__ float flg2_exact(float x) {
    int bi = __float_as_int(x);
    float m = __int_as_float((bi & 0x007fffff) | 0x3f800000);
    float e = (float)((bi >> 23) - 127);
    float lm;
    asm("lg2.approx.f32 %0, %1;" : "=f"(lm) : "f"(m));
    return lm + e;
}

__device__ __forceinline__ unsigned long long pk2(float a, float b) {
    unsigned long long r;
    asm("mov.b64 %0, {%1, %2};" : "=l"(r) : "f"(a), "f"(b));
    return r;
}
__device__ __forceinline__ void upk2(unsigned long long v, float& a, float& b) {
    asm("mov.b64 {%0, %1}, %2;" : "=f"(a), "=f"(b) : "l"(v));
}
__device__ __forceinline__ unsigned long long ffma2(unsigned long long a,
                                                    unsigned long long b,
                                                    unsigned long long c) {
    unsigned long long r;
    asm("fma.rn.f32x2 %0, %1, %2, %3;" : "=l"(r) : "l"(a), "l"(b), "l"(c));
    return r;
}
__device__ __forceinline__ unsigned long long fadd2(unsigned long long a,
                                                    unsigned long long b) {
    unsigned long long r;
    asm("add.rn.f32x2 %0, %1, %2;" : "=l"(r) : "l"(a), "l"(b));
    return r;
}

#define CP16(dst, src) \
    asm volatile("cp.async.cg.shared.global [%0], [%1], 16;" :: "r"(dst), "l"(src))

// ---------------------------------------------------------------------------
// Phase 1: 296 persistent workers = 2 CTAs on each of 148 SMs.
// Worker w: dt = w/37 (d-tile of 64), r = w%37; chunks c = r, r+37, ... of
// KC=32 k each; running per-(b,d) argmin in registers.
// 3-deep cp.async ring: stage s+2 issued while s is consumed (prefetch
// distance ~2 stages > queue-inflated DRAM latency).
// Per stage: 4 k-rows of the [32w x 64d] tile, rows rotated by 8*(w>>3)
// floats -> conflict-free LDS. lane = g*8 + ds; thread owns one d, 8 w,
// 8 b (NEGATED exact query logs cached packed over b-pairs).
// Per k: 8 LDS + 8 MUFU + 8 FMA(self, 2 chains) + 8 mov + 32 FFMA2, then
// packed halving butterfly; each lane argmins 2 scalars (its b-pair).
// ---------------------------------------------------------------------------
__global__ __launch_bounds__(256, 2)
void knw_phase1(const float* __restrict__ query,
                const float* __restrict__ qtext) {
    extern __shared__ float tile[];              // [NBUF][STAGE_K][TILE_F]

    const int wkr   = blockIdx.x;                // 0..295
    const int dt    = wkr / NWORK;
    const int r     = wkr - dt * NWORK;
    const int nch   = (r < 34) ? 7 : 6;          // 34*7 + 3*6 = 256 chunks
    const int nst   = nch * SPC;

    const int tid   = threadIdx.x;
    const int lane  = tid & 31;
    const int g     = lane >> 3;
    const int ds    = lane & 7;
    const int w_id  = tid >> 5;
    const int dl    = w_id * 8 + ds;
    const int d     = dt * DTILE + dl;
    const int w0    = g * 8;
    const int bh    = g & 1;                     // xor-8 partner flips
    const int bh2   = (g >> 1) & 1;              // xor-16 partner flips
    const int bbase = 4 * bh + 2 * bh2;          // final owned b-pair base

    // NEGATED exact lg2(query[b][w][d]), 8 w x 8 b packed over b-pairs.
    unsigned long long lq2[4][8];
    #pragma unroll
    for (int j = 0; j < 8; j++) {
        const int w = w0 + j;
        #pragma unroll
        for (int bp = 0; bp < 4; bp++) {
            float a = -flg2_exact(query[((2 * bp)     * WNUM + w) * TDIM + d]);
            float b = -flg2_exact(query[((2 * bp + 1) * WNUM + w) * TDIM + d]);
            lq2[bp][j] = pk2(a, b);
        }
    }

    // Staging: thread handles 16B chunks m = tid, tid+256 per k.
    const int w_a = tid >> 4,         c_a = tid & 15;
    const int w_b = (tid + 256) >> 4, c_b = (tid + 256) & 15;
    const int doff_a = (w_a * 64 + (((c_a + 2 * (w_a >> 3)) & 15) << 2)) * 4;
    const int doff_b = (w_b * 64 + (((c_b + 2 * (w_b >> 3)) & 15) << 2)) * 4;
    const long soff_a = ((long)w_a * TDIM + dt * DTILE + c_a * 4) * 4;
    const long soff_b = ((long)w_b * TDIM + dt * DTILE + c_b * 4) * 4;

    const unsigned tile_u32 = (unsigned)__cvta_generic_to_shared(tile);
    const long KROW = (long)WNUM * TDIM * 4;     // bytes per k

    auto stage_k0 = [&](int s) {
        return (r + NWORK * (s >> 3)) * KC + (s & 7) * STAGE_K;
    };
    auto issue_stage = [&](int s, int buf) {
        const char* src = (const char*)qtext + (long)stage_k0(s) * KROW;
        const unsigned dbase = tile_u32 + buf * (STAGE_K * TILE_F * 4);
        #pragma unroll
        for (int ki = 0; ki < STAGE_K; ki++) {
            CP16(dbase + ki * (TILE_F * 4) + doff_a, src + ki * KROW + soff_a);
            CP16(dbase + ki * (TILE_F * 4) + doff_b, src + ki * KROW + soff_b);
        }
        asm volatile("cp.async.commit_group;");
    };

    issue_stage(0, 0);
    issue_stage(1, 1);

    float minv0 = __int_as_float(0x7f800000), minv1 = minv0;
    int   mini0 = 0, mini1 = 0;

    const int pbase = g * 512 + ((dl + 8 * g) & 63);   // LDS base (floats)

    int buf = 0;                                 // rotating buffer index = s % 3
    int nbuf2 = 2;                               // (s+2) % 3

    #pragma unroll 1
    for (int s = 0; s < nst; s++) {
        if (s + 2 < nst) {
            issue_stage(s + 2, nbuf2);
            asm volatile("cp.async.wait_group 2;");
        } else if (s + 1 < nst) {
            asm volatile("cp.async.wait_group 1;");
        } else {
            asm volatile("cp.async.wait_group 0;");
        }
        __syncthreads();

        const float* bufp = tile + buf * (STAGE_K * TILE_F);
        const int k0 = stage_k0(s);

        #pragma unroll
        for (int ki = 0; ki < STAGE_K; ki++) {
            const float* tp = bufp + ki * TILE_F;

            float x[8];
            #pragma unroll
            for (int j = 0; j < 8; j++) x[j] = tp[pbase + j * 64];

            float sacc_e = 0.0f, sacc_o = 0.0f;  // split self chains
            unsigned long long c2[4];
            #pragma unroll
            for (int bp = 0; bp < 4; bp++) c2[bp] = 0ull;

            #pragma unroll
            for (int j = 0; j < 8; j++) {
                const float xv = x[j];
                const float l  = flg2_fast(xv);          // 1 MUFU
                if (j & 1) sacc_o = fmaf(xv, l, sacc_o);
                else       sacc_e = fmaf(xv, l, sacc_e);
                const unsigned long long xx = pk2(xv, xv);
                #pragma unroll
                for (int bp = 0; bp < 4; bp++)
                    c2[bp] = ffma2(xx, lq2[bp][j], c2[bp]);   // += x * (-lq)
            }
            const float sacc = sacc_e + sacc_o;

            // o2[bp] = sacc + c_bp (packed b-pairs; c holds negated cross).
            const unsigned long long ss = pk2(sacc, sacc);
            unsigned long long o2[4];
            #pragma unroll
            for (int bp = 0; bp < 4; bp++) o2[bp] = fadd2(ss, c2[bp]);

            // r1 (xor 8): partner has opposite bh; keep own 2 pairs, send 2.
            unsigned long long s0 = bh ? o2[0] : o2[2];
            unsigned long long s1 = bh ? o2[1] : o2[3];
            unsigned long long k0p = bh ? o2[2] : o2[0];
            unsigned long long k1p = bh ? o2[3] : o2[1];
            unsigned long long h0 = fadd2(k0p, __shfl_xor_sync(0xffffffffu, s0, 8));
            unsigned long long h1 = fadd2(k1p, __shfl_xor_sync(0xffffffffu, s1, 8));

            // r2 (xor 16): partner same bh, opposite bh2; keep 1 pair, send 1.
            unsigned long long s2 = bh2 ? h0 : h1;
            unsigned long long k2 = bh2 ? h1 : h0;
            unsigned long long hf = fadd2(k2, __shfl_xor_sync(0xffffffffu, s2, 16));

            float ha, hb;
            upk2(hf, ha, hb);

            const int kglob = k0 + ki;
            bool p0 = ha < minv0;               // strict <: earliest k wins
            bool p1 = hb < minv1;
            minv0 = fminf(ha, minv0);
            minv1 = fminf(hb, minv1);
            mini0 = p0 ? kglob : mini0;
            mini1 = p1 ? kglob : mini1;
        }
        __syncthreads();

        buf   = (buf   == 2) ? 0 : buf + 1;
        nbuf2 = (nbuf2 == 2) ? 0 : nbuf2 + 1;
    }

    // Every lane owns b-pair (bbase, bbase+1) for its d: 32 lanes cover
    // 8 d x 8 b exactly once.
    g_pval[r][bbase][d]     = minv0;
    g_pidx[r][bbase][d]     = mini0;
    g_pval[r][bbase + 1][d] = minv1;
    g_pidx[r][bbase + 1][d] = mini1;
}

// ---------------------------------------------------------------------------
// Phase 2a: reduce NWORK partial argmins -> g_idx[b*512+d].
// Workers hold interleaved k-sets: break value ties by smaller k.
// ---------------------------------------------------------------------------
__global__ __launch_bounds__(256)
void knw_phase2a() {
    const int bd = blockIdx.x * 256 + threadIdx.x;
    const int b  = bd >> 9;
    const int d  = bd & 511;
    float bv = __int_as_float(0x7f800000);
    int   bi = 0x7fffffff;
    #pragma unroll
    for (int r = 0; r < NWORK; r++) {
        float v = g_pval[r][b][d];
        int   i = g_pidx[r][b][d];
        if (v < bv || (v == bv && i < bi)) { bv = v; bi = i; }
    }
    g_idx[bd] = bi;
}

// ---------------------------------------------------------------------------
// Phase 2b: 2 CTAs per (b,d) row (half-row each). Index loaded once (L1
// broadcast); 3 independent LDG.128 per thread; streaming stores keep the
// gathered qvideo rows resident in L2.
// ---------------------------------------------------------------------------
#define ROW_F4 (FNUM * VDIM / 4)   // 1536 float4 per row
__global__ __launch_bounds__(256)
void knw_phase2b(const float* __restrict__ qvideo, float* __restrict__ out) {
    const int bd   = blockIdx.x >> 1;            // 0..4095
    const int half = blockIdx.x & 1;
    const int k    = g_idx[bd];
    const int off  = half * (ROW_F4 / 2);
    const float4* __restrict__ src =
        (const float4*)qvideo + (size_t)k * ROW_F4 + off;
    float4* __restrict__ dst = (float4*)out + (size_t)bd * ROW_F4 + off;
    const int t = threadIdx.x;
    float4 v[3];
    #pragma unroll
    for (int u = 0; u < 3; u++) v[u] = src[t + u * 256];
    #pragma unroll
    for (int u = 0; u < 3; u++) __stcs(&dst[t + u * 256], v[u]);
}

extern "C" void kernel_launch(void* const* d_in, const int* in_sizes, int n_in,
                              void* d_out, int out_size) {
    const float* query  = (const float*)d_in[0];   // [8, 32, 512]
    const float* qtext  = (const float*)d_in[1];   // [8192, 32, 512]
    const float* qvideo = (const float*)d_in[2];   // [8192, 12, 512]
    float* out = (float*)d_out;                    // [8, 512, 12, 512]

    cudaFuncSetAttribute(knw_phase1,
                         cudaFuncAttributeMaxDynamicSharedMemorySize, SMEM_BYTES);

    knw_phase1<<<NDTILE * NWORK, 256, SMEM_BYTES>>>(query, qtext);
    knw_phase2a<<<BATCH * TDIM / 256, 256>>>();
    knw_phase2b<<<BATCH * TDIM * 2, 256>>>(qvideo, out);
}